// round 1
// baseline (speedup 1.0000x reference)
#include <cuda_runtime.h>

// Problem constants
#define B_  64
#define H_  1024
#define I_  1024
#define BH  (B_ * H_)          // 65536
#define BHI ((size_t)BH * I_)  // 67108864

// Coefficient scratch (no cudaMalloc allowed): 3 x 256 KB
__device__ float g_common[BH];
__device__ float g_zf[BH];
__device__ float g_fz[BH];

// ---------------------------------------------------------------------------
// Kernel A: gate GEMV + scalar gate math. One warp per (b,h).
// ---------------------------------------------------------------------------
__global__ void __launch_bounds__(256) gates_kernel(
    const float* __restrict__ x,            // [B, I]
    const float* __restrict__ hidden_prev,  // [B, H]
    const float* __restrict__ wz_state,     // [B, H]
    const float* __restrict__ wf_state,     // [B, H]
    const float* __restrict__ bz_state,     // [B, H]
    const float* __restrict__ bf_state,     // [B, H]
    const float* __restrict__ wm_z,         // [H, I]
    const float* __restrict__ wm_f,         // [H, I]
    const float* __restrict__ wv_z,         // [H]
    const float* __restrict__ wv_f,         // [H]
    const float* __restrict__ bias_z,       // [H]
    const float* __restrict__ bias_f,       // [H]
    float* __restrict__ out_cell,           // [B, H]
    float* __restrict__ out_wz,
    float* __restrict__ out_wf,
    float* __restrict__ out_bz,
    float* __restrict__ out_bf)
{
    const int w    = (blockIdx.x * blockDim.x + threadIdx.x) >> 5;  // (b,h) index
    const int lane = threadIdx.x & 31;
    if (w >= BH) return;

    const int b = w >> 10;      // / H
    const int h = w & (H_ - 1); // % H

    const float4* xb  = reinterpret_cast<const float4*>(x + (size_t)b * I_);
    const float4* wzr = reinterpret_cast<const float4*>(wm_z + (size_t)h * I_);
    const float4* wfr = reinterpret_cast<const float4*>(wm_f + (size_t)h * I_);

    float az = 0.f, af = 0.f;
    #pragma unroll
    for (int i = lane; i < I_ / 4; i += 32) {
        float4 xv = __ldg(xb + i);
        float4 wz = __ldg(wzr + i);
        float4 wf = __ldg(wfr + i);
        az += xv.x * wz.x + xv.y * wz.y + xv.z * wz.z + xv.w * wz.w;
        af += xv.x * wf.x + xv.y * wf.y + xv.z * wf.z + xv.w * wf.w;
    }
    #pragma unroll
    for (int o = 16; o > 0; o >>= 1) {
        az += __shfl_down_sync(0xffffffffu, az, o);
        af += __shfl_down_sync(0xffffffffu, af, o);
    }

    if (lane == 0) {
        const float hp  = hidden_prev[w];
        const float vz  = wv_z[h];
        const float vf  = wv_f[h];
        const float z   = tanhf(az + vz * hp + bias_z[h]);
        const float fpre = af + vf * hp + bias_f[h];
        const float f   = 1.f / (1.f + expf(-fpre));

        const float new_cell = hp * f + (1.f - f) * z;
        const float zf = (1.f - f) * (1.f - z * z);
        const float fz = (hp - z) * (1.f - f) * f;
        const float common = f + zf * vz + fz * vf;

        out_cell[w] = new_cell;
        out_wz[w]   = hp * zf + common * wz_state[w];
        out_wf[w]   = hp * fz + common * wf_state[w];
        out_bz[w]   = zf + common * bz_state[w];
        out_bf[w]   = fz + common * bf_state[w];

        g_common[w] = common;
        g_zf[w]     = zf;
        g_fz[w]     = fz;
    }
}

// ---------------------------------------------------------------------------
// Kernel B: Z_new / F_new streaming update. One thread per float4; each
// thread handles both Z and F to amortize coefficient + x loads.
// ---------------------------------------------------------------------------
__global__ void __launch_bounds__(256) state_kernel(
    const float4* __restrict__ Z,    // [B*H*I/4]
    const float4* __restrict__ F,
    const float4* __restrict__ x4,   // [B*I/4]
    float4* __restrict__ Zo,
    float4* __restrict__ Fo)
{
    const int idx = blockIdx.x * blockDim.x + threadIdx.x;  // 0 .. B*H*I/4-1
    const int row = idx >> 8;          // (b*H + h),  I/4 = 256
    const int i4  = idx & 255;
    const int b   = row >> 10;

    const float c  = __ldg(&g_common[row]);
    const float zf = __ldg(&g_zf[row]);
    const float fz = __ldg(&g_fz[row]);
    const float4 xv = __ldg(&x4[(b << 8) + i4]);

    const float4 zv = Z[idx];
    const float4 fv = F[idx];

    float4 zo, fo;
    zo.x = c * zv.x + zf * xv.x;
    zo.y = c * zv.y + zf * xv.y;
    zo.z = c * zv.z + zf * xv.z;
    zo.w = c * zv.w + zf * xv.w;
    fo.x = c * fv.x + fz * xv.x;
    fo.y = c * fv.y + fz * xv.y;
    fo.z = c * fv.z + fz * xv.z;
    fo.w = c * fv.w + fz * xv.w;

    Zo[idx] = zo;
    Fo[idx] = fo;
}

// ---------------------------------------------------------------------------
extern "C" void kernel_launch(void* const* d_in, const int* in_sizes, int n_in,
                              void* d_out, int out_size)
{
    const float* x           = (const float*)d_in[0];
    const float* hidden_prev = (const float*)d_in[1];
    const float* Z_state     = (const float*)d_in[2];
    const float* F_state     = (const float*)d_in[3];
    const float* wz_state    = (const float*)d_in[4];
    const float* wf_state    = (const float*)d_in[5];
    const float* bz_state    = (const float*)d_in[6];
    const float* bf_state    = (const float*)d_in[7];
    const float* wm_z        = (const float*)d_in[8];
    const float* wm_f        = (const float*)d_in[9];
    const float* wv_z        = (const float*)d_in[10];
    const float* wv_f        = (const float*)d_in[11];
    const float* bias_z      = (const float*)d_in[12];
    const float* bias_f      = (const float*)d_in[13];

    float* out = (float*)d_out;
    // Output tuple layout: new_cell, Z_new, F_new, wz_new, wf_new, bz_new, bf_new
    float* o_cell = out;
    float* o_Z    = out + BH;
    float* o_F    = o_Z + BHI;
    float* o_wz   = o_F + BHI;
    float* o_wf   = o_wz + BH;
    float* o_bz   = o_wf + BH;
    float* o_bf   = o_bz + BH;

    // Kernel A: 65536 warps -> 8192 blocks of 256 threads
    gates_kernel<<<(BH * 32) / 256, 256>>>(
        x, hidden_prev, wz_state, wf_state, bz_state, bf_state,
        wm_z, wm_f, wv_z, wv_f, bias_z, bias_f,
        o_cell, o_wz, o_wf, o_bz, o_bf);

    // Kernel B: B*H*I/4 = 16,777,216 float4 threads
    const int total4 = (int)(BHI / 4);
    state_kernel<<<total4 / 256, 256>>>(
        (const float4*)Z_state, (const float4*)F_state, (const float4*)x,
        (float4*)o_Z, (float4*)o_F);
}